// round 17
// baseline (speedup 1.0000x reference)
#include <cuda_runtime.h>
#include <cuda_bf16.h>

// Quanvolutional layer, single fused kernel.
// inputs:  (16, 3, 32, 32) float32
// weights: (16, 3, 16)     float32
// output:  (16, 16, 31, 31) float32  [B, O, Hp, Wp]
//
// Per block (one output channel o): fast preamble computes weight trig/tan/F
// in smem. Per thread: 12 pixel loads + 12 __sincosf hoisted BEFORE the
// barrier (MUFU overlaps preamble), then pruned tan-RY circuits (pure FMA).

#define HP 31
#define WP 31
#define NPOS (16 * HP * WP)      // 15376 positions (b,h,w)

// Heavy circuits first so the tail wave is made of cheap blocks.
__constant__ int c_omap[16] = {3, 8, 13, 4, 9, 14, 2, 7, 12, 0, 5, 10, 15, 1, 6, 11};
// Which weight indices are applied as tan-RYs per circuit class (o%5).
__constant__ unsigned c_tanmask[5] = {0x0010u, 0x0000u, 0x0010u, 0x9FF0u, 0x0FF0u};

// Tan-form RY on wire W: s0' = s0 - t*s1 ; s1' = s1 + t*s0 (1 FMA each).
template <int W>
__device__ __forceinline__ void ryt(float s[16], float t) {
    constexpr int bit = 8 >> W;
#pragma unroll
    for (int i = 0; i < 16; i++) {
        if ((i & bit) == 0) {
            float a = s[i], b = s[i | bit];
            s[i]       = fmaf(-t, b, a);
            s[i | bit] = fmaf(t, a, b);
        }
    }
}

// CNOT: compile-time register permutation (zero SASS cost).
template <int C, int T>
__device__ __forceinline__ void cx(float s[16]) {
    constexpr int cb = 8 >> C, tb = 8 >> T;
#pragma unroll
    for (int i = 0; i < 16; i++) {
        if ((i & cb) && !(i & tb)) {
            float tmp = s[i]; s[i] = s[i | tb]; s[i | tb] = tmp;
        }
    }
}

// Rotate pixel half-angle trig by weight half angle (angle addition).
__device__ __forceinline__ float2 fuse(float2 x, float2 w) {
    return make_float2(x.x * w.x - x.y * w.y, x.y * w.x + x.x * w.y);
}

__device__ __forceinline__ void embed(float s[16], float2 a0, float2 a1,
                                      float2 a2, float2 a3) {
    float p01[4] = { a0.x * a1.x, a0.x * a1.y, a0.y * a1.x, a0.y * a1.y };
    float p23[4] = { a2.x * a3.x, a2.x * a3.y, a2.y * a3.x, a2.y * a3.y };
#pragma unroll
    for (int q = 0; q < 16; q++) s[q] = p01[q >> 2] * p23[q & 3];
}

// (sum_{wire0=0} s^2) - (sum_{wire0=1} s^2), unnormalized.
__device__ __forceinline__ float expz0(const float s[16]) {
    float ep = 0.0f, en = 0.0f;
#pragma unroll
    for (int q = 0; q < 16; q++) {
        if (q & 8) en = fmaf(s[q], s[q], en);
        else       ep = fmaf(s[q], s[q], ep);
    }
    return ep - en;
}

__global__ __launch_bounds__(128, 4) void quanv_kernel(const float* __restrict__ in,
                                                       const float* __restrict__ wt,
                                                       float* __restrict__ out) {
    const int o = c_omap[blockIdx.y];
    const int circ = o % 5;

    __shared__ float2 wfu[3][4];   // (cos,sin) half-angle of w0..w3
    __shared__ float  wtn[3][16];  // tan(w_j/2)
    __shared__ float  wF[3];       // (prod cos over tan-RY set)^2

    // Preamble (48 threads): fast-path trig; fully overlapped by the pixel
    // loads + sincos below in the other warps.
    if (threadIdx.x < 48) {
        int c = threadIdx.x >> 4, j = threadIdx.x & 15;
        float sn, cs;
        __sincosf(0.5f * wt[(o * 3 + c) * 16 + j], &sn, &cs);
        if (j < 4) wfu[c][j] = make_float2(cs, sn);
        float csn = fabsf(cs) < 1e-20f ? (cs < 0.0f ? -1e-20f : 1e-20f) : cs;
        wtn[c][j] = __fdividef(sn, csn);
        unsigned mask = c_tanmask[circ];
        float f = (mask >> j & 1u) ? csn * csn : 1.0f;
        unsigned sm = (threadIdx.x < 32) ? 0xFFFFFFFFu : 0x0000FFFFu;
#pragma unroll
        for (int d = 1; d < 16; d <<= 1)
            f *= __shfl_xor_sync(sm, f, d);
        if (j == 0) wF[c] = f;
    }

    int p = blockIdx.x * blockDim.x + threadIdx.x;
    bool live = (p < NPOS);
    int pc = live ? p : 0;
    int b  = pc / (HP * WP);
    int hw = pc - b * (HP * WP);
    int h  = hw / WP;
    int w  = hw - h * WP;

    // Load 12 pixels (MLP=12) and run all 12 __sincosf BEFORE the barrier:
    // MUFU latency + load latency hide behind the preamble + barrier.
    float2 pt[3][4];
    {
        const float* base = in + ((b * 3) * 32 + h) * 32 + w;
#pragma unroll
        for (int c = 0; c < 3; c++) {
            const float* ip = base + c * 1024;
            float x0 = ip[0], x1 = ip[1], x2 = ip[32], x3 = ip[33];
            __sincosf(0.5f * x0, &pt[c][0].y, &pt[c][0].x);
            __sincosf(0.5f * x1, &pt[c][1].y, &pt[c][1].x);
            __sincosf(0.5f * x2, &pt[c][2].y, &pt[c][2].x);
            __sincosf(0.5f * x3, &pt[c][3].y, &pt[c][3].x);
        }
    }

    __syncthreads();
    if (!live) return;

    float acc = 0.0f;

#pragma unroll
    for (int c = 0; c < 3; c++) {
        const float2* WU = wfu[c];
        const float*  T  = wtn[c];
        const float   F  = wF[c];

        switch (circ) {
            case 0: {  // ran -> wires {0,1}: fused ry0,ry1; cx01; tan-ry0(w4)
                float2 a0 = fuse(pt[c][0], WU[0]);
                float2 a1 = fuse(pt[c][1], WU[1]);
                float t4 = T[4];
                float t00 = a0.x * a1.x, t01 = a0.x * a1.y;
                float t10 = a0.y * a1.y, t11 = a0.y * a1.x;
                float n00 = fmaf(-t4, t10, t00), n10 = fmaf(t4, t00, t10);
                float n01 = fmaf(-t4, t11, t01), n11 = fmaf(t4, t01, t11);
                float d = n00 * n00 + n01 * n01 - n10 * n10 - n11 * n11;
                acc = fmaf(F, d, acc);
                break;
            }
            case 1: {  // line -> single qubit: <Z0> = cos(x0 + w0)
                float2 a0 = fuse(pt[c][0], WU[0]);
                acc += a0.x * a0.x - a0.y * a0.y;   // F == 1
                break;
            }
            case 2: {  // ring -> fused embed, 4 CNOTs, tan-ry0(w4)
                float s[16];
                embed(s, fuse(pt[c][0], WU[0]), fuse(pt[c][1], WU[1]),
                         fuse(pt[c][2], WU[2]), fuse(pt[c][3], WU[3]));
                cx<0, 1>(s); cx<1, 2>(s); cx<2, 3>(s); cx<3, 0>(s);
                ryt<0>(s, T[4]);
                acc = fmaf(F, expz0(s), acc);
                break;
            }
            case 3: {  // doublering -> fused embed; 10 tan-RYs; pruned tail
                float s[16];
                embed(s, fuse(pt[c][0], WU[0]), fuse(pt[c][1], WU[1]),
                         fuse(pt[c][2], WU[2]), fuse(pt[c][3], WU[3]));
                cx<0, 1>(s); cx<1, 2>(s); cx<2, 3>(s); cx<3, 0>(s);
                ryt<0>(s, T[4]); ryt<1>(s, T[5]); ryt<2>(s, T[6]); ryt<3>(s, T[7]);
                cx<3, 0>(s); cx<2, 3>(s); cx<1, 2>(s); cx<0, 1>(s);
                ryt<0>(s, T[8]); ryt<1>(s, T[9]); ryt<2>(s, T[10]); ryt<3>(s, T[11]);
                cx<0, 1>(s); cx<1, 2>(s); cx<2, 3>(s); cx<3, 0>(s);
                ryt<0>(s, T[12]);   // ry1(w13), ry2(w14) pruned
                ryt<3>(s, T[15]);
                cx<3, 0>(s);        // trailing cx23,cx12,cx01 pruned
                acc = fmaf(F, expz0(s), acc);
                break;
            }
            default: {  // blockring -> fused embed; 8 tan-RYs
                float s[16];
                embed(s, fuse(pt[c][0], WU[0]), fuse(pt[c][1], WU[1]),
                         fuse(pt[c][2], WU[2]), fuse(pt[c][3], WU[3]));
                cx<0, 1>(s); cx<2, 3>(s); cx<1, 2>(s); cx<3, 0>(s);
                ryt<0>(s, T[4]); ryt<1>(s, T[5]); ryt<2>(s, T[6]); ryt<3>(s, T[7]);
                cx<0, 1>(s); cx<2, 3>(s); cx<1, 2>(s); cx<3, 0>(s);
                ryt<0>(s, T[8]); ryt<1>(s, T[9]); ryt<2>(s, T[10]); ryt<3>(s, T[11]);
                cx<0, 1>(s); cx<2, 3>(s); cx<1, 2>(s); cx<3, 0>(s);
                acc = fmaf(F, expz0(s), acc);
                break;
            }
        }
    }

    out[((b * 16 + o) * HP + h) * WP + w] = acc;
}

extern "C" void kernel_launch(void* const* d_in, const int* in_sizes, int n_in,
                              void* d_out, int out_size) {
    const float* in = (const float*)d_in[0];   // (16,3,32,32)
    const float* w  = (const float*)d_in[1];   // (16,3,16)
    float* out = (float*)d_out;                // (16,16,31,31)

    dim3 grid((NPOS + 127) / 128, 16);         // 121 x 16 blocks, ONE kernel
    quanv_kernel<<<grid, 128>>>(in, w, out);
}